// round 3
// baseline (speedup 1.0000x reference)
#include <cuda_runtime.h>
#include <cstdint>
#include <cstddef>

#define Bz 8192
#define Nz 64
#define Dz 256
#define Hz 8
#define HHz 32
#define KTOT (Hz*Dz) /* 2048 */

typedef unsigned long long ull;

// ---------------- scratch (static device globals; no allocations) ----------
__device__ float g_wnb[Hz*Dz];            // 8KB
__device__ float g_wcur[Hz*Dz];           // 8KB
__device__ float g_M2[(size_t)KTOT*Dz];   // 2MB   [k][e], k = h*256+d
__device__ float g_G[(size_t)Bz*KTOT];    // 64MB  [b][h*256+d]

// ---------------- packed f32x2 helpers (FFMA2) -----------------------------
__device__ __forceinline__ ull pack2(float x, float y){
    ull r;
    asm("mov.b64 %0, {%1, %2};" : "=l"(r) : "f"(x), "f"(y));
    return r;
}
__device__ __forceinline__ void fma2(ull &acc, ull a, ull b){
    asm("fma.rn.f32x2 %0, %1, %2, %0;" : "+l"(acc) : "l"(a), "l"(b));
}
__device__ __forceinline__ float2 unpack2(ull v){
    float lo, hi;
    asm("mov.b64 {%0, %1}, %2;" : "=f"(lo), "=f"(hi) : "l"(v));
    return make_float2(lo, hi);
}
__device__ __forceinline__ float red2(ull v){
    float2 p = unpack2(v);
    return p.x + p.y;
}

// ---------------- K1a: wcur[h,:], wnb[h,:] ---------------------------------
__global__ void prep_vecs_kernel(const float* __restrict__ W,
                                 const float* __restrict__ cur_a,
                                 const float* __restrict__ nb_a){
    int h = blockIdx.x, d = threadIdx.x;
    float sc = 0.f, sn = 0.f;
    #pragma unroll
    for (int j = 0; j < HHz; j++){
        float w = W[(h*HHz + j)*Dz + d];
        sc += cur_a[h*HHz + j] * w;
        sn += nb_a [h*HHz + j] * w;
    }
    g_wcur[h*Dz + d] = sc;
    g_wnb [h*Dz + d] = sn;
}

// ---------------- K1b: M2[(h,d),e] = sum_j W[h*32+j,d]*W_out[e,h*32+j] -----
__global__ void prep_M2_kernel(const float* __restrict__ W,
                               const float* __restrict__ W_out){
    int k = blockIdx.x;              // 0..2047
    int h = k >> 8, d = k & 255;
    __shared__ float sW[HHz];
    int t = threadIdx.x;             // e = t
    if (t < HHz) sW[t] = W[(h*HHz + t)*Dz + d];
    __syncthreads();
    float acc = 0.f;
    const float* wo = W_out + (size_t)t*Dz + h*HHz;
    #pragma unroll
    for (int j = 0; j < HHz; j++) acc += sW[j] * wo[j];
    g_M2[(size_t)k*Dz + t] = acc;
}

// ---------------- K2: fused attention per batch ----------------------------
// grid = 8192, block = 256 (8 warps).
// smem: swizzled inter tile (64KB) + wnb (8KB) + scores (2KB) + cur (32B)
#define SMEM_ATTN ((Nz*Dz + Hz*Dz + Nz*Hz + Hz) * 4)

__global__ __launch_bounds__(256)
void attn_kernel(const float* __restrict__ inter,
                 const int*   __restrict__ lengths,
                 float*       __restrict__ out){
    extern __shared__ float smem[];
    float* s_inter = smem;                 // [64][256], f4-swizzled by n&7
    float* s_wnb   = smem + Nz*Dz;         // [8][256],  f4-swizzled by h
    float* s_sc    = s_wnb + Hz*Dz;        // [64][8]  scores -> attn (in place)
    float* s_cur   = s_sc + Nz*Hz;         // [8]

    int b = blockIdx.x;
    int t = threadIdx.x;
    int w = t >> 5, l = t & 31;

    // ---- load inter_info[b] tile (coalesced), store XOR-swizzled ----
    {
        const float4* src = (const float4*)(inter + (size_t)b*Nz*Dz);
        float4* dst = (float4*)s_inter;
        #pragma unroll
        for (int i = 0; i < 16; i++){
            int g  = t + 256*i;
            int n  = g >> 6, c4 = g & 63;
            dst[n*64 + (c4 ^ (n & 7))] = src[g];
        }
        // wnb: 2048 floats = 512 float4, swizzled by h
        const float4* wsrc = (const float4*)g_wnb;
        float4* wdst = (float4*)s_wnb;
        #pragma unroll
        for (int i = 0; i < 2; i++){
            int g = t + 256*i;
            int h = g >> 6, c4 = g & 63;
            wdst[h*64 + (c4 ^ h)] = wsrc[g];
        }
    }
    __syncthreads();

    // ---- scores: thread t -> head h = t&7, rows n0 = t>>3 and n0+32 -------
    {
        int h  = t & 7;
        int n0 = t >> 3, n1 = n0 + 32;
        int sw = n0 & 7;                 // n1&7 == n0&7
        const ulonglong2* W4 = (const ulonglong2*)s_wnb   + h*64;
        const ulonglong2* X0 = (const ulonglong2*)s_inter + n0*64;
        const ulonglong2* X1 = (const ulonglong2*)s_inter + n1*64;

        ull a0x=0, a0y=0, a1x=0, a1y=0;
        #pragma unroll
        for (int c8 = 0; c8 < 64; c8 += 8){
            #pragma unroll
            for (int j = 0; j < 8; j++){
                ulonglong2 wv = W4[c8 + (j ^ h)];
                ulonglong2 x0 = X0[c8 + (j ^ sw)];
                ulonglong2 x1 = X1[c8 + (j ^ sw)];
                fma2(a0x, wv.x, x0.x); fma2(a0y, wv.y, x0.y);
                fma2(a1x, wv.x, x1.x); fma2(a1y, wv.y, x1.y);
            }
        }
        s_sc[n0*Hz + h] = red2(a0x) + red2(a0y);
        s_sc[n1*Hz + h] = red2(a1x) + red2(a1y);

        // cur score: only threads 0..7 (n0 == 0, sw == 0)
        if (t < 8){
            const ulonglong2* WC = (const ulonglong2*)g_wcur + h*64;
            ull cx=0, cy=0;
            #pragma unroll
            for (int c4 = 0; c4 < 64; c4++){
                ulonglong2 wc = WC[c4];
                ulonglong2 x0 = X0[c4];
                fma2(cx, wc.x, x0.x); fma2(cy, wc.y, x0.y);
            }
            s_cur[h] = red2(cx) + red2(cy);
        }
    }
    __syncthreads();

    // ---- softmax per head: warp w owns head h = w (in-place on s_sc) ----
    {
        int h = w;
        float c = s_cur[h];
        int len = lengths[b]; if (len < 1) len = 1;

        float v0 = c + s_sc[l*Hz + h];
        float v1 = c + s_sc[(l + 32)*Hz + h];
        v0 = v0 > 0.f ? v0 : 0.01f*v0;
        v1 = v1 > 0.f ? v1 : 0.01f*v1;
        bool m0 = (l < len), m1 = ((l + 32) < len);
        float y0 = m0 ? v0 : -3.0e38f;
        float y1 = m1 ? v1 : -3.0e38f;
        float mx = fmaxf(y0, y1);
        #pragma unroll
        for (int off = 16; off > 0; off >>= 1)
            mx = fmaxf(mx, __shfl_xor_sync(0xffffffffu, mx, off));
        float e0 = m0 ? __expf(v0 - mx) : 0.f;
        float e1 = m1 ? __expf(v1 - mx) : 0.f;
        float s = e0 + e1;
        #pragma unroll
        for (int off = 16; off > 0; off >>= 1)
            s += __shfl_xor_sync(0xffffffffu, s, off);
        float inv = 1.f / s;
        s_sc[l*Hz + h]        = e0 * inv;
        s_sc[(l + 32)*Hz + h] = e1 * inv;
    }
    __syncthreads();

    // ---- G[b,h,d] = sum_n attn[n,h] * inter[n,d]; also copy query row ----
    {
        int d = t;
        float acc[8];
        #pragma unroll
        for (int h = 0; h < 8; h++) acc[h] = 0.f;
        #pragma unroll 8
        for (int n = 0; n < Nz; n++){
            float4 a0 = *(float4*)(s_sc + n*Hz);
            float4 a1 = *(float4*)(s_sc + n*Hz + 4);
            float x = s_inter[n*Dz + (d ^ ((n & 7) << 2))];
            acc[0] += a0.x*x; acc[1] += a0.y*x; acc[2] += a0.z*x; acc[3] += a0.w*x;
            acc[4] += a1.x*x; acc[5] += a1.y*x; acc[6] += a1.z*x; acc[7] += a1.w*x;
        }
        float* Gp = g_G + (size_t)b*KTOT;
        #pragma unroll
        for (int h = 0; h < 8; h++) Gp[h*Dz + d] = acc[h];
        // batch_query_info = inter_info[:,0]  (row 0 has swizzle 0)
        out[(size_t)Bz*Dz + (size_t)b*Dz + d] = s_inter[d];
    }
}

// ---------------- K3: out1 = G (8192x2048) @ M2 (2048x256) -----------------
// BM=BN=64, KC=32 -> 512 blocks. A-tile stored pre-duplicated as (a,a) ull
// pairs so the inner loop is pure LDS + FFMA2 (no pack MOVs).
#define BM3 64
#define BN3 64
#define KC3 32

__global__ __launch_bounds__(256)
void out_gemm_kernel(float* __restrict__ out){
    __shared__ ull   GsD[KC3][BM3 + 1];   // stride 65 ull = 520B (conflict-free STS64)
    __shared__ float Ms[KC3][BN3];

    int t  = threadIdx.x;
    int tx = t & 15, ty = t >> 4;         // 16x16 thread tile, 4x4 outputs each
    int row0 = blockIdx.x * BM3;
    int col0 = blockIdx.y * BN3;

    // loader indices
    int lr = t >> 2;              // G row within tile (0..63)
    int lk = (t & 3) * 8;         // k chunk base (0,8,16,24)
    int mk = t >> 3;              // M2 k row (0..31)
    int mc = (t & 7) * 4;         // M2 col offset (second half at +32)

    ull acc[4][2];
    #pragma unroll
    for (int i = 0; i < 4; i++){ acc[i][0] = 0ull; acc[i][1] = 0ull; }

    const float* Gp = g_G + (size_t)(row0 + lr)*KTOT + lk;
    const float* Mp = g_M2 + (size_t)mk*Dz + col0 + mc;

    // prefetch tile 0
    float4 gva = *(const float4*)(Gp);
    float4 gvb = *(const float4*)(Gp + 4);
    float4 mva = *(const float4*)(Mp);
    float4 mvb = *(const float4*)(Mp + 32);

    for (int k0 = 0; k0 < KTOT; k0 += KC3){
        // stage into smem (A duplicated)
        GsD[lk+0][lr] = pack2(gva.x, gva.x);
        GsD[lk+1][lr] = pack2(gva.y, gva.y);
        GsD[lk+2][lr] = pack2(gva.z, gva.z);
        GsD[lk+3][lr] = pack2(gva.w, gva.w);
        GsD[lk+4][lr] = pack2(gvb.x, gvb.x);
        GsD[lk+5][lr] = pack2(gvb.y, gvb.y);
        GsD[lk+6][lr] = pack2(gvb.z, gvb.z);
        GsD[lk+7][lr] = pack2(gvb.w, gvb.w);
        *(float4*)&Ms[mk][mc]      = mva;
        *(float4*)&Ms[mk][mc + 32] = mvb;
        __syncthreads();

        // prefetch next tile while computing
        if (k0 + KC3 < KTOT){
            const float* gp = Gp + k0 + KC3;
            gva = *(const float4*)(gp);
            gvb = *(const float4*)(gp + 4);
            const float* mp = Mp + (size_t)(k0 + KC3)*Dz;
            mva = *(const float4*)(mp);
            mvb = *(const float4*)(mp + 32);
        }

        #pragma unroll
        for (int kk = 0; kk < KC3; kk++){
            ull a0 = GsD[kk][ty*4 + 0];
            ull a1 = GsD[kk][ty*4 + 1];
            ull a2 = GsD[kk][ty*4 + 2];
            ull a3 = GsD[kk][ty*4 + 3];
            ulonglong2 bv = *(ulonglong2*)&Ms[kk][tx*4];
            fma2(acc[0][0], a0, bv.x); fma2(acc[0][1], a0, bv.y);
            fma2(acc[1][0], a1, bv.x); fma2(acc[1][1], a1, bv.y);
            fma2(acc[2][0], a2, bv.x); fma2(acc[2][1], a2, bv.y);
            fma2(acc[3][0], a3, bv.x); fma2(acc[3][1], a3, bv.y);
        }
        __syncthreads();
    }

    #pragma unroll
    for (int i = 0; i < 4; i++){
        float2 p0 = unpack2(acc[i][0]);
        float2 p1 = unpack2(acc[i][1]);
        float4 v = make_float4(p0.x, p0.y, p1.x, p1.y);
        *(float4*)(out + (size_t)(row0 + ty*4 + i)*Dz + col0 + tx*4) = v;
    }
}

// ---------------- launch ----------------------------------------------------
extern "C" void kernel_launch(void* const* d_in, const int* in_sizes, int n_in,
                              void* d_out, int out_size){
    const float* inter   = (const float*)d_in[0];
    const int*   lengths = (const int*)  d_in[1];
    const float* W       = (const float*)d_in[2];
    const float* cur_a   = (const float*)d_in[3];
    const float* nb_a    = (const float*)d_in[4];
    const float* W_out   = (const float*)d_in[5];
    float* out = (float*)d_out;

    cudaFuncSetAttribute(attn_kernel, cudaFuncAttributeMaxDynamicSharedMemorySize, SMEM_ATTN);

    prep_vecs_kernel<<<Hz, Dz>>>(W, cur_a, nb_a);
    prep_M2_kernel<<<KTOT, Dz>>>(W, W_out);
    attn_kernel<<<Bz, 256, SMEM_ATTN>>>(inter, lengths, out);
    dim3 g3(Bz/BM3, Dz/BN3);
    out_gemm_kernel<<<g3, 256>>>(out);
}

// round 5
// speedup vs baseline: 1.5395x; 1.5395x over previous
#include <cuda_runtime.h>
#include <cuda_bf16.h>
#include <cstdint>
#include <cstddef>

#define Bz 8192
#define Nz 64
#define Dz 256
#define Hz 8
#define HHz 32
#define KTOT (Hz*Dz) /* 2048 */

typedef unsigned long long ull;

// ---------------- scratch (static device globals; no allocations) ----------
__device__ float g_wnb[Hz*Dz];
__device__ float g_wcur[Hz*Dz];
__device__ __nv_bfloat16 g_M2Th[(size_t)Dz*KTOT];   // 1MB  M2^T hi [e][k]
__device__ __nv_bfloat16 g_M2Tl[(size_t)Dz*KTOT];   // 1MB  M2^T lo [e][k]
__device__ __nv_bfloat16 g_Gh[(size_t)Bz*KTOT];     // 32MB G hi [b][k]
__device__ __nv_bfloat16 g_Gl[(size_t)Bz*KTOT];     // 32MB G lo [b][k]

// ---------------- packed f32x2 helpers -------------------------------------
__device__ __forceinline__ ull pack2(float x, float y){
    ull r; asm("mov.b64 %0, {%1, %2};" : "=l"(r) : "f"(x), "f"(y)); return r;
}
__device__ __forceinline__ void fma2(ull &acc, ull a, ull b){
    asm("fma.rn.f32x2 %0, %1, %2, %0;" : "+l"(acc) : "l"(a), "l"(b));
}
__device__ __forceinline__ float2 unpack2(ull v){
    float lo, hi; asm("mov.b64 {%0, %1}, %2;" : "=f"(lo), "=f"(hi) : "l"(v));
    return make_float2(lo, hi);
}
__device__ __forceinline__ float red2(ull v){ float2 p = unpack2(v); return p.x + p.y; }

__device__ __forceinline__ uint32_t smem_u32(const void* p){
    uint32_t a;
    asm("{ .reg .u64 t; cvta.to.shared.u64 t, %1; cvt.u32.u64 %0, t; }" : "=r"(a) : "l"(p));
    return a;
}

// ---------------- legacy tensor-path wrappers (sm_80+, no 'a' features) ----
__device__ __forceinline__ void ldm_x4(uint32_t &r0, uint32_t &r1, uint32_t &r2,
                                       uint32_t &r3, uint32_t addr){
    asm volatile("ldmatrix.sync.aligned.m8n8.x4.shared.b16 {%0,%1,%2,%3}, [%4];"
                 : "=r"(r0), "=r"(r1), "=r"(r2), "=r"(r3) : "r"(addr));
}
__device__ __forceinline__ void mma_bf16(float* c, const uint32_t* a,
                                         uint32_t b0, uint32_t b1){
    asm volatile(
        "mma.sync.aligned.m16n8k16.row.col.f32.bf16.bf16.f32 "
        "{%0,%1,%2,%3}, {%4,%5,%6,%7}, {%8,%9}, {%0,%1,%2,%3};"
        : "+f"(c[0]), "+f"(c[1]), "+f"(c[2]), "+f"(c[3])
        : "r"(a[0]), "r"(a[1]), "r"(a[2]), "r"(a[3]), "r"(b0), "r"(b1));
}
__device__ __forceinline__ void cpasync16(uint32_t dst, const void* src){
    asm volatile("cp.async.cg.shared.global [%0], [%1], 16;" :: "r"(dst), "l"(src) : "memory");
}
#define CP_COMMIT() asm volatile("cp.async.commit_group;" ::: "memory")
#define CP_WAIT(n)  asm volatile("cp.async.wait_group %0;" :: "n"(n) : "memory")

// ---------------- K1a: wcur[h,:], wnb[h,:] ---------------------------------
__global__ void prep_vecs_kernel(const float* __restrict__ W,
                                 const float* __restrict__ cur_a,
                                 const float* __restrict__ nb_a){
    int h = blockIdx.x, d = threadIdx.x;
    float sc = 0.f, sn = 0.f;
    #pragma unroll
    for (int j = 0; j < HHz; j++){
        float w = W[(h*HHz + j)*Dz + d];
        sc += cur_a[h*HHz + j] * w;
        sn += nb_a [h*HHz + j] * w;
    }
    g_wcur[h*Dz + d] = sc;
    g_wnb [h*Dz + d] = sn;
}

// ---------------- K1b: M2T[e][k] hi/lo bf16 --------------------------------
__global__ void prep_M2_kernel(const float* __restrict__ W,
                               const float* __restrict__ W_out){
    int k = blockIdx.x;              // 0..2047
    int h = k >> 8, d = k & 255;
    __shared__ float sW[HHz];
    int t = threadIdx.x;             // e = t
    if (t < HHz) sW[t] = W[(h*HHz + t)*Dz + d];
    __syncthreads();
    float acc = 0.f;
    const float* wo = W_out + (size_t)t*Dz + h*HHz;
    #pragma unroll
    for (int j = 0; j < HHz; j++) acc += sW[j] * wo[j];
    __nv_bfloat16 hb = __float2bfloat16(acc);
    float lo = acc - __bfloat162float(hb);
    g_M2Th[(size_t)t*KTOT + k] = hb;
    g_M2Tl[(size_t)t*KTOT + k] = __float2bfloat16(lo);
}

// ---------------- K2: fused attention per batch ----------------------------
#define SMEM_ATTN ((Nz*Dz + Hz*Dz + Nz*Hz + Hz) * 4)

__global__ __launch_bounds__(256)
void attn_kernel(const float* __restrict__ inter,
                 const int*   __restrict__ lengths,
                 float*       __restrict__ out){
    extern __shared__ float smem[];
    float* s_inter = smem;                 // [64][256], f4-swizzled by n&7
    float* s_wnb   = smem + Nz*Dz;         // [8][256],  f4-swizzled by h
    float* s_sc    = s_wnb + Hz*Dz;        // [64][8]
    float* s_cur   = s_sc + Nz*Hz;         // [8]

    int b = blockIdx.x;
    int t = threadIdx.x;
    int w = t >> 5, l = t & 31;

    {
        const float4* src = (const float4*)(inter + (size_t)b*Nz*Dz);
        float4* dst = (float4*)s_inter;
        #pragma unroll
        for (int i = 0; i < 16; i++){
            int g  = t + 256*i;
            int n  = g >> 6, c4 = g & 63;
            dst[n*64 + (c4 ^ (n & 7))] = src[g];
        }
        const float4* wsrc = (const float4*)g_wnb;
        float4* wdst = (float4*)s_wnb;
        #pragma unroll
        for (int i = 0; i < 2; i++){
            int g = t + 256*i;
            int h = g >> 6, c4 = g & 63;
            wdst[h*64 + (c4 ^ h)] = wsrc[g];
        }
    }
    __syncthreads();

    {
        int h  = t & 7;
        int n0 = t >> 3, n1 = n0 + 32;
        int sw = n0 & 7;
        const ulonglong2* W4 = (const ulonglong2*)s_wnb   + h*64;
        const ulonglong2* X0 = (const ulonglong2*)s_inter + n0*64;
        const ulonglong2* X1 = (const ulonglong2*)s_inter + n1*64;

        ull a0x=0, a0y=0, a1x=0, a1y=0;
        #pragma unroll
        for (int c8 = 0; c8 < 64; c8 += 8){
            #pragma unroll
            for (int j = 0; j < 8; j++){
                ulonglong2 wv = W4[c8 + (j ^ h)];
                ulonglong2 x0 = X0[c8 + (j ^ sw)];
                ulonglong2 x1 = X1[c8 + (j ^ sw)];
                fma2(a0x, wv.x, x0.x); fma2(a0y, wv.y, x0.y);
                fma2(a1x, wv.x, x1.x); fma2(a1y, wv.y, x1.y);
            }
        }
        s_sc[n0*Hz + h] = red2(a0x) + red2(a0y);
        s_sc[n1*Hz + h] = red2(a1x) + red2(a1y);

        if (t < 8){
            const ulonglong2* WC = (const ulonglong2*)g_wcur + h*64;
            ull cx=0, cy=0;
            #pragma unroll
            for (int c4 = 0; c4 < 64; c4++){
                ulonglong2 wc = WC[c4];
                ulonglong2 x0 = X0[c4];
                fma2(cx, wc.x, x0.x); fma2(cy, wc.y, x0.y);
            }
            s_cur[h] = red2(cx) + red2(cy);
        }
    }
    __syncthreads();

    {
        int h = w;
        float c = s_cur[h];
        int len = lengths[b]; if (len < 1) len = 1;

        float v0 = c + s_sc[l*Hz + h];
        float v1 = c + s_sc[(l + 32)*Hz + h];
        v0 = v0 > 0.f ? v0 : 0.01f*v0;
        v1 = v1 > 0.f ? v1 : 0.01f*v1;
        bool m0 = (l < len), m1 = ((l + 32) < len);
        float y0 = m0 ? v0 : -3.0e38f;
        float y1 = m1 ? v1 : -3.0e38f;
        float mx = fmaxf(y0, y1);
        #pragma unroll
        for (int off = 16; off > 0; off >>= 1)
            mx = fmaxf(mx, __shfl_xor_sync(0xffffffffu, mx, off));
        float e0 = m0 ? __expf(v0 - mx) : 0.f;
        float e1 = m1 ? __expf(v1 - mx) : 0.f;
        float s = e0 + e1;
        #pragma unroll
        for (int off = 16; off > 0; off >>= 1)
            s += __shfl_xor_sync(0xffffffffu, s, off);
        float inv = 1.f / s;
        s_sc[l*Hz + h]        = e0 * inv;
        s_sc[(l + 32)*Hz + h] = e1 * inv;
    }
    __syncthreads();

    {
        int d = t;
        float acc[8];
        #pragma unroll
        for (int h = 0; h < 8; h++) acc[h] = 0.f;
        #pragma unroll 8
        for (int n = 0; n < Nz; n++){
            float4 a0 = *(float4*)(s_sc + n*Hz);
            float4 a1 = *(float4*)(s_sc + n*Hz + 4);
            float x = s_inter[n*Dz + (d ^ ((n & 7) << 2))];
            acc[0] += a0.x*x; acc[1] += a0.y*x; acc[2] += a0.z*x; acc[3] += a0.w*x;
            acc[4] += a1.x*x; acc[5] += a1.y*x; acc[6] += a1.z*x; acc[7] += a1.w*x;
        }
        __nv_bfloat16* Gh = g_Gh + (size_t)b*KTOT;
        __nv_bfloat16* Gl = g_Gl + (size_t)b*KTOT;
        #pragma unroll
        for (int h = 0; h < 8; h++){
            float v  = acc[h];
            __nv_bfloat16 hb = __float2bfloat16(v);
            float lo = v - __bfloat162float(hb);
            Gh[h*Dz + d] = hb;
            Gl[h*Dz + d] = __float2bfloat16(lo);
        }
        out[(size_t)Bz*Dz + (size_t)b*Dz + d] = s_inter[d];
    }
}

// ---------------- K3: bf16 mma.sync GEMM  out1 = G @ M2T^T -----------------
// Tiles: BM=128, BN=128, BK=32. 8 warps (4 m x 2 n), warp tile 32x64.
// 3-term bf16 split: D += Ah*Bh + Ah*Bl + Al*Bh. cp.async double buffer.
// smem tile layout: row r (64B of 32 bf16) packed 2 rows / 128B line with
// XOR swizzle: addr = line*128 + (((r&1)*4 + j) ^ (line&7))*16, line=r>>1.
#define STG_BYTES 32768
#define SMEM_G3 (2*STG_BYTES)

__global__ __launch_bounds__(256)
void out_gemm_kernel(float* __restrict__ out){
    extern __shared__ char smem3[];
    uint32_t sb = smem_u32(smem3);
    int t = threadIdx.x;
    int wid = t >> 5, l = t & 31;
    int wm = wid & 3, wn = wid >> 2;
    int row0 = blockIdx.x * 128;
    int col0 = blockIdx.y * 128;

    // ---- loader setup: thread covers tile tt, 8 x 16B chunks per stage ----
    int tt = t >> 6;         // 0:Ah 1:Al 2:Bh 3:Bl
    int q0 = t & 63;
    const char* srcbase;
    {
        const char* p;
        if      (tt == 0) p = (const char*)(g_Gh)   + (size_t)row0*4096;
        else if (tt == 1) p = (const char*)(g_Gl)   + (size_t)row0*4096;
        else if (tt == 2) p = (const char*)(g_M2Th) + (size_t)col0*4096;
        else              p = (const char*)(g_M2Tl) + (size_t)col0*4096;
        srcbase = p;
    }
    uint32_t dsw[8]; size_t soff[8];
    #pragma unroll
    for (int i = 0; i < 8; i++){
        int q = q0 + 64*i;
        int row = q >> 2, j = q & 3;
        int line = row >> 1;
        dsw[i] = (uint32_t)(tt*8192 + line*128 + ((((row & 1)*4 + j) ^ (line & 7))*16));
        soff[i] = (size_t)row*4096 + (size_t)j*16;
    }

    // ---- ldmatrix address offsets (within a stage) ----
    uint32_t offA[2][2], offB[4][2];
    {
        int lr8 = ((l >> 3) & 1)*8 + (l & 7);
        int jj = l >> 4;
        #pragma unroll
        for (int mi = 0; mi < 2; mi++){
            int row = wm*32 + mi*16 + lr8;
            int line = row >> 1;
            #pragma unroll
            for (int ks = 0; ks < 2; ks++)
                offA[mi][ks] = (uint32_t)(line*128 + ((((row & 1)*4 + 2*ks + jj) ^ (line & 7))*16));
        }
        #pragma unroll
        for (int g = 0; g < 4; g++){
            int row = wn*64 + g*16 + lr8;
            int line = row >> 1;
            #pragma unroll
            for (int ks = 0; ks < 2; ks++)
                offB[g][ks] = (uint32_t)(line*128 + ((((row & 1)*4 + 2*ks + jj) ^ (line & 7))*16));
        }
    }

    float acc[2][8][4];
    #pragma unroll
    for (int mi = 0; mi < 2; mi++)
        #pragma unroll
        for (int na = 0; na < 8; na++)
            #pragma unroll
            for (int i = 0; i < 4; i++) acc[mi][na][i] = 0.f;

    // ---- prologue: stage 0 ----
    #pragma unroll
    for (int i = 0; i < 8; i++)
        cpasync16(sb + dsw[i], srcbase + soff[i]);
    CP_COMMIT();

    for (int c = 0; c < 64; c++){
        int p = c & 1;
        if (c + 1 < 64){
            uint32_t stg = sb + ((c + 1) & 1)*STG_BYTES;
            const char* s2 = srcbase + (size_t)(c + 1)*64;
            #pragma unroll
            for (int i = 0; i < 8; i++)
                cpasync16(stg + dsw[i], s2 + soff[i]);
            CP_COMMIT();
            CP_WAIT(1);
        } else {
            CP_WAIT(0);
        }
        __syncthreads();

        uint32_t base = sb + p*STG_BYTES;
        uint32_t Ah = base, Al = base + 8192, Bh = base + 16384, Bl = base + 24576;
        #pragma unroll
        for (int ks = 0; ks < 2; ks++){
            uint32_t ah[2][4], al[2][4], bh[4][4], bl[4][4];
            #pragma unroll
            for (int mi = 0; mi < 2; mi++){
                ldm_x4(ah[mi][0], ah[mi][1], ah[mi][2], ah[mi][3], Ah + offA[mi][ks]);
                ldm_x4(al[mi][0], al[mi][1], al[mi][2], al[mi][3], Al + offA[mi][ks]);
            }
            #pragma unroll
            for (int g = 0; g < 4; g++){
                ldm_x4(bh[g][0], bh[g][1], bh[g][2], bh[g][3], Bh + offB[g][ks]);
                ldm_x4(bl[g][0], bl[g][1], bl[g][2], bl[g][3], Bl + offB[g][ks]);
            }
            #pragma unroll
            for (int mi = 0; mi < 2; mi++){
                #pragma unroll
                for (int na = 0; na < 8; na++){
                    int g = na >> 1, o = na & 1;
                    mma_bf16(acc[mi][na], ah[mi], bh[g][o], bh[g][o + 2]);
                    mma_bf16(acc[mi][na], ah[mi], bl[g][o], bl[g][o + 2]);
                    mma_bf16(acc[mi][na], al[mi], bh[g][o], bh[g][o + 2]);
                }
            }
        }
        __syncthreads();
    }

    // ---- epilogue ----
    #pragma unroll
    for (int mi = 0; mi < 2; mi++){
        #pragma unroll
        for (int na = 0; na < 8; na++){
            int r  = row0 + wm*32 + mi*16 + (l >> 2);
            int cc = col0 + wn*64 + na*8 + (l & 3)*2;
            *(float2*)(out + (size_t)r*Dz + cc)       = make_float2(acc[mi][na][0], acc[mi][na][1]);
            *(float2*)(out + (size_t)(r + 8)*Dz + cc) = make_float2(acc[mi][na][2], acc[mi][na][3]);
        }
    }
}

// ---------------- launch ----------------------------------------------------
extern "C" void kernel_launch(void* const* d_in, const int* in_sizes, int n_in,
                              void* d_out, int out_size){
    const float* inter   = (const float*)d_in[0];
    const int*   lengths = (const int*)  d_in[1];
    const float* W       = (const float*)d_in[2];
    const float* cur_a   = (const float*)d_in[3];
    const float* nb_a    = (const float*)d_in[4];
    const float* W_out   = (const float*)d_in[5];
    float* out = (float*)d_out;

    cudaFuncSetAttribute(attn_kernel, cudaFuncAttributeMaxDynamicSharedMemorySize, SMEM_ATTN);
    cudaFuncSetAttribute(out_gemm_kernel, cudaFuncAttributeMaxDynamicSharedMemorySize, SMEM_G3);

    prep_vecs_kernel<<<Hz, Dz>>>(W, cur_a, nb_a);
    prep_M2_kernel<<<KTOT, Dz>>>(W, W_out);
    attn_kernel<<<Bz, 256, SMEM_ATTN>>>(inter, lengths, out);
    dim3 g3(Bz/128, Dz/128);
    out_gemm_kernel<<<g3, 256, SMEM_G3>>>(out);
}

// round 6
// speedup vs baseline: 1.9244x; 1.2500x over previous
#include <cuda_runtime.h>
#include <cuda_bf16.h>
#include <cstdint>
#include <cstddef>

#define Bz 8192
#define Nz 64
#define Dz 256
#define Hz 8
#define HHz 32
#define KTOT (Hz*Dz) /* 2048 */

typedef unsigned long long ull;

// ---------------- scratch (static device globals; no allocations) ----------
__device__ __nv_bfloat16 g_wv_h[16*Dz];             // [j][d] j:0-7 wnb, 8-15 wcur
__device__ __nv_bfloat16 g_wv_l[16*Dz];
__device__ __nv_bfloat16 g_M2Th[(size_t)Dz*KTOT];   // 1MB  M2^T hi [e][k]
__device__ __nv_bfloat16 g_M2Tl[(size_t)Dz*KTOT];   // 1MB  M2^T lo [e][k]
__device__ __nv_bfloat16 g_Gh[(size_t)Bz*KTOT];     // 32MB G hi [b][k]
__device__ __nv_bfloat16 g_Gl[(size_t)Bz*KTOT];     // 32MB G lo [b][k]

// ---------------- helpers ---------------------------------------------------
__device__ __forceinline__ uint32_t smem_u32(const void* p){
    uint32_t a;
    asm("{ .reg .u64 t; cvta.to.shared.u64 t, %1; cvt.u32.u64 %0, t; }" : "=r"(a) : "l"(p));
    return a;
}
__device__ __forceinline__ void ldm_x4(uint32_t &r0, uint32_t &r1, uint32_t &r2,
                                       uint32_t &r3, uint32_t addr){
    asm volatile("ldmatrix.sync.aligned.m8n8.x4.shared.b16 {%0,%1,%2,%3}, [%4];"
                 : "=r"(r0), "=r"(r1), "=r"(r2), "=r"(r3) : "r"(addr));
}
__device__ __forceinline__ void ldm_x4_t(uint32_t &r0, uint32_t &r1, uint32_t &r2,
                                         uint32_t &r3, uint32_t addr){
    asm volatile("ldmatrix.sync.aligned.m8n8.x4.trans.shared.b16 {%0,%1,%2,%3}, [%4];"
                 : "=r"(r0), "=r"(r1), "=r"(r2), "=r"(r3) : "r"(addr));
}
__device__ __forceinline__ void mma_bf16(float* c, const uint32_t* a,
                                         uint32_t b0, uint32_t b1){
    asm volatile(
        "mma.sync.aligned.m16n8k16.row.col.f32.bf16.bf16.f32 "
        "{%0,%1,%2,%3}, {%4,%5,%6,%7}, {%8,%9}, {%0,%1,%2,%3};"
        : "+f"(c[0]), "+f"(c[1]), "+f"(c[2]), "+f"(c[3])
        : "r"(a[0]), "r"(a[1]), "r"(a[2]), "r"(a[3]), "r"(b0), "r"(b1));
}
__device__ __forceinline__ void cpasync16(uint32_t dst, const void* src){
    asm volatile("cp.async.cg.shared.global [%0], [%1], 16;" :: "r"(dst), "l"(src) : "memory");
}
#define CP_COMMIT() asm volatile("cp.async.commit_group;" ::: "memory")
#define CP_WAIT(n)  asm volatile("cp.async.wait_group %0;" :: "n"(n) : "memory")

__device__ __forceinline__ uint32_t bf16pack(float a, float b){
    unsigned short u0 = __bfloat16_as_ushort(__float2bfloat16(a));
    unsigned short u1 = __bfloat16_as_ushort(__float2bfloat16(b));
    return (uint32_t)u0 | ((uint32_t)u1 << 16);
}

// ---------------- K1a: combined score vectors, bf16 hi/lo ------------------
__global__ void prep_vecs_kernel(const float* __restrict__ W,
                                 const float* __restrict__ cur_a,
                                 const float* __restrict__ nb_a){
    int j = blockIdx.x;          // 0..15
    int d = threadIdx.x;
    int h = j & 7;
    const float* av = (j < 8) ? (nb_a + h*HHz) : (cur_a + h*HHz);
    float s = 0.f;
    #pragma unroll
    for (int k = 0; k < HHz; k++)
        s += av[k] * W[(h*HHz + k)*Dz + d];
    __nv_bfloat16 hb = __float2bfloat16(s);
    float lo = s - __bfloat162float(hb);
    g_wv_h[j*Dz + d] = hb;
    g_wv_l[j*Dz + d] = __float2bfloat16(lo);
}

// ---------------- K1b: M2T[e][k] hi/lo bf16 --------------------------------
__global__ void prep_M2_kernel(const float* __restrict__ W,
                               const float* __restrict__ W_out){
    int k = blockIdx.x;              // 0..2047
    int h = k >> 8, d = k & 255;
    __shared__ float sW[HHz];
    int t = threadIdx.x;             // e = t
    if (t < HHz) sW[t] = W[(h*HHz + t)*Dz + d];
    __syncthreads();
    float acc = 0.f;
    const float* wo = W_out + (size_t)t*Dz + h*HHz;
    #pragma unroll
    for (int j = 0; j < HHz; j++) acc += sW[j] * wo[j];
    __nv_bfloat16 hb = __float2bfloat16(acc);
    float lo = acc - __bfloat162float(hb);
    g_M2Th[(size_t)t*KTOT + k] = hb;
    g_M2Tl[(size_t)t*KTOT + k] = __float2bfloat16(lo);
}

// ---------------- K2: tensor-core fused attention --------------------------
// smem byte offsets
#define O_XH 0
#define O_XL 32768
#define O_WH 65536
#define O_WL 73728
#define O_SS 81920              /* f32 [64][17] = 4352B */
#define O_AH 86272              /* bf16 [16][64] swizzled, 2048B */
#define O_AL 88320
#define SMEM_ATTN 90368

__global__ __launch_bounds__(256)
void attn_kernel(const float* __restrict__ inter,
                 const int*   __restrict__ lengths,
                 float*       __restrict__ out){
    extern __shared__ char smem[];
    uint32_t sb = smem_u32(smem);
    float* sS = (float*)(smem + O_SS);

    int b = blockIdx.x;
    int t = threadIdx.x;
    int wid = t >> 5, l = t & 31;
    int l7 = l & 7;
    int lr8 = ((l >> 3) & 1)*8 + l7;
    int jj4 = l >> 4;

    // ---- load X (f32 -> bf16 hi/lo, swizzled), copy query row ----
    {
        const float4* src = (const float4*)(inter + (size_t)b*Nz*Dz);
        #pragma unroll
        for (int i = 0; i < 16; i++){
            int g  = t + 256*i;
            int n  = g >> 6, c4 = g & 63;
            float4 v = src[g];
            uint32_t off = (uint32_t)(n*512 + (((c4 >> 1) ^ (n & 7)) << 4) + (c4 & 1)*8);
            float hx = __bfloat162float(__float2bfloat16(v.x));
            float hy = __bfloat162float(__float2bfloat16(v.y));
            float hz = __bfloat162float(__float2bfloat16(v.z));
            float hw = __bfloat162float(__float2bfloat16(v.w));
            uint2 hiP = make_uint2(bf16pack(v.x, v.y), bf16pack(v.z, v.w));
            uint2 loP = make_uint2(bf16pack(v.x - hx, v.y - hy), bf16pack(v.z - hz, v.w - hw));
            *(uint2*)(smem + O_XH + off) = hiP;
            *(uint2*)(smem + O_XL + off) = loP;
            if (n == 0)
                *(float4*)(out + (size_t)Bz*Dz + (size_t)b*Dz + c4*4) = v;
        }
        // W tiles: 512 chunks of 16B each array
        #pragma unroll
        for (int i = 0; i < 2; i++){
            int c = t + 256*i;
            int row = c >> 5, cc = c & 31;
            uint32_t off = (uint32_t)(row*512 + ((cc ^ (row & 7)) << 4));
            *(uint4*)(smem + O_WH + off) = ((const uint4*)g_wv_h)[c];
            *(uint4*)(smem + O_WL + off) = ((const uint4*)g_wv_l)[c];
        }
    }
    __syncthreads();

    // ---- score phase: S(64x16) = X(64x256) . W^T, 3-term bf16 split ----
    {
        int wm = wid >> 1;           // m-tile (16 seq rows)
        int wn = wid & 1;            // n-tile (8 score cols)
        uint32_t aH = sb + O_XH + (uint32_t)((wm*16 + lr8)*512);
        uint32_t aL = sb + O_XL + (uint32_t)((wm*16 + lr8)*512);
        uint32_t bH = sb + O_WH + (uint32_t)((wn*8 + l7)*512);
        uint32_t bL = sb + O_WL + (uint32_t)((wn*8 + l7)*512);

        float c[4] = {0.f, 0.f, 0.f, 0.f};
        #pragma unroll
        for (int kk2 = 0; kk2 < 8; kk2++){
            uint32_t bq = kk2*4 + (l >> 3);
            uint32_t bo = ((bq ^ l7) << 4);
            uint32_t bh[4], bl[4];
            ldm_x4(bh[0], bh[1], bh[2], bh[3], bH + bo);
            ldm_x4(bl[0], bl[1], bl[2], bl[3], bL + bo);
            #pragma unroll
            for (int s = 0; s < 2; s++){
                int kk = kk2*2 + s;
                uint32_t ao = (((uint32_t)(kk*2 + jj4) ^ l7) << 4);
                uint32_t ah[4], al[4];
                ldm_x4(ah[0], ah[1], ah[2], ah[3], aH + ao);
                ldm_x4(al[0], al[1], al[2], al[3], aL + ao);
                mma_bf16(c, ah, bh[2*s], bh[2*s + 1]);
                mma_bf16(c, ah, bl[2*s], bl[2*s + 1]);
                mma_bf16(c, al, bh[2*s], bh[2*s + 1]);
            }
        }
        int r0 = wm*16 + (l >> 2);
        int jc = wn*8 + (l & 3)*2;
        sS[r0*17 + jc]         = c[0];
        sS[r0*17 + jc + 1]     = c[1];
        sS[(r0 + 8)*17 + jc]     = c[2];
        sS[(r0 + 8)*17 + jc + 1] = c[3];
    }
    __syncthreads();

    // ---- softmax per head (warp w = head h), write attn bf16 hi/lo ----
    {
        // zero attn rows 8..15 (padding for m16 MMA)
        ((uint32_t*)(smem + O_AH))[256 + t] = 0u;
        ((uint32_t*)(smem + O_AL))[256 + t] = 0u;

        int h = wid;
        float cur = sS[8 + h];   // row 0, col 8+h
        int len = lengths[b]; if (len < 1) len = 1;

        float v0 = cur + sS[l*17 + h];
        float v1 = cur + sS[(l + 32)*17 + h];
        v0 = v0 > 0.f ? v0 : 0.01f*v0;
        v1 = v1 > 0.f ? v1 : 0.01f*v1;
        bool m0 = (l < len), m1 = ((l + 32) < len);
        float y0 = m0 ? v0 : -3.0e38f;
        float y1 = m1 ? v1 : -3.0e38f;
        float mx = fmaxf(y0, y1);
        #pragma unroll
        for (int off = 16; off > 0; off >>= 1)
            mx = fmaxf(mx, __shfl_xor_sync(0xffffffffu, mx, off));
        float e0 = m0 ? __expf(v0 - mx) : 0.f;
        float e1 = m1 ? __expf(v1 - mx) : 0.f;
        float s = e0 + e1;
        #pragma unroll
        for (int off = 16; off > 0; off >>= 1)
            s += __shfl_xor_sync(0xffffffffu, s, off);
        float inv = 1.f / s;
        float a0 = e0 * inv, a1 = e1 * inv;

        // swizzled store: [h][n], chunk swz by h
        int hs = h & 7;
        #pragma unroll
        for (int q = 0; q < 2; q++){
            int n = l + 32*q;
            float a = q ? a1 : a0;
            __nv_bfloat16 hb = __float2bfloat16(a);
            float lo = a - __bfloat162float(hb);
            uint32_t off = (uint32_t)(h*128 + (((n >> 3) ^ hs) << 4) + (n & 7)*2);
            *(__nv_bfloat16*)(smem + O_AH + off) = hb;
            *(__nv_bfloat16*)(smem + O_AL + off) = __float2bfloat16(lo);
        }
    }
    __syncthreads();

    // ---- G phase: G(16x256) = attn^T(16x64) . X(64x256), warp = 32 d ----
    {
        float g[4][4];
        #pragma unroll
        for (int i = 0; i < 4; i++)
            #pragma unroll
            for (int j = 0; j < 4; j++) g[i][j] = 0.f;

        uint32_t aHb = sb + O_AH + (uint32_t)(lr8*128);
        uint32_t aLb = sb + O_AL + (uint32_t)(lr8*128);

        #pragma unroll
        for (int ks = 0; ks < 4; ks++){
            uint32_t ao = (((uint32_t)(ks*2 + jj4) ^ l7) << 4);
            uint32_t ah[4], al[4];
            ldm_x4(ah[0], ah[1], ah[2], ah[3], aHb + ao);
            ldm_x4(al[0], al[1], al[2], al[3], aLb + ao);

            uint32_t rowb = (uint32_t)((ks*16 + lr8)*512);
            #pragma unroll
            for (int pair = 0; pair < 2; pair++){
                uint32_t ch = (uint32_t)(wid*4 + pair*2 + jj4);
                uint32_t xo = rowb + ((ch ^ l7) << 4);
                uint32_t xh[4], xl[4];
                ldm_x4_t(xh[0], xh[1], xh[2], xh[3], sb + O_XH + xo);
                ldm_x4_t(xl[0], xl[1], xl[2], xl[3], sb + O_XL + xo);
                mma_bf16(g[pair*2 + 0], ah, xh[0], xh[1]);
                mma_bf16(g[pair*2 + 0], ah, xl[0], xl[1]);
                mma_bf16(g[pair*2 + 0], al, xh[0], xh[1]);
                mma_bf16(g[pair*2 + 1], ah, xh[2], xh[3]);
                mma_bf16(g[pair*2 + 1], ah, xl[2], xl[3]);
                mma_bf16(g[pair*2 + 1], al, xh[2], xh[3]);
            }
        }

        int h = l >> 2;              // 0..7 (rows 8-15 of C are zero padding)
        uint32_t* Gh = (uint32_t*)(g_Gh + (size_t)b*KTOT);
        uint32_t* Gl = (uint32_t*)(g_Gl + (size_t)b*KTOT);
        #pragma unroll
        for (int i = 0; i < 4; i++){
            int d = wid*32 + i*8 + (l & 3)*2;
            float x0 = g[i][0], x1 = g[i][1];
            float h0 = __bfloat162float(__float2bfloat16(x0));
            float h1 = __bfloat162float(__float2bfloat16(x1));
            uint32_t idx = (uint32_t)(h*256 + d) >> 1;
            Gh[idx] = bf16pack(x0, x1);
            Gl[idx] = bf16pack(x0 - h0, x1 - h1);
        }
    }
}

// ---------------- K3: bf16 mma.sync GEMM  out1 = G @ M2T^T -----------------
#define STG_BYTES 32768
#define SMEM_G3 (2*STG_BYTES)

__global__ __launch_bounds__(256)
void out_gemm_kernel(float* __restrict__ out){
    extern __shared__ char smem3[];
    uint32_t sb = smem_u32(smem3);
    int t = threadIdx.x;
    int wid = t >> 5, l = t & 31;
    int wm = wid & 3, wn = wid >> 2;
    int row0 = blockIdx.x * 128;
    int col0 = blockIdx.y * 128;

    int tt = t >> 6;
    int q0 = t & 63;
    const char* srcbase;
    {
        const char* p;
        if      (tt == 0) p = (const char*)(g_Gh)   + (size_t)row0*4096;
        else if (tt == 1) p = (const char*)(g_Gl)   + (size_t)row0*4096;
        else if (tt == 2) p = (const char*)(g_M2Th) + (size_t)col0*4096;
        else              p = (const char*)(g_M2Tl) + (size_t)col0*4096;
        srcbase = p;
    }
    uint32_t dsw[8]; size_t soff[8];
    #pragma unroll
    for (int i = 0; i < 8; i++){
        int q = q0 + 64*i;
        int row = q >> 2, j = q & 3;
        int line = row >> 1;
        dsw[i] = (uint32_t)(tt*8192 + line*128 + ((((row & 1)*4 + j) ^ (line & 7))*16));
        soff[i] = (size_t)row*4096 + (size_t)j*16;
    }

    uint32_t offA[2][2], offB[4][2];
    {
        int lr8 = ((l >> 3) & 1)*8 + (l & 7);
        int jj = l >> 4;
        #pragma unroll
        for (int mi = 0; mi < 2; mi++){
            int row = wm*32 + mi*16 + lr8;
            int line = row >> 1;
            #pragma unroll
            for (int ks = 0; ks < 2; ks++)
                offA[mi][ks] = (uint32_t)(line*128 + ((((row & 1)*4 + 2*ks + jj) ^ (line & 7))*16));
        }
        #pragma unroll
        for (int g = 0; g < 4; g++){
            int row = wn*64 + g*16 + lr8;
            int line = row >> 1;
            #pragma unroll
            for (int ks = 0; ks < 2; ks++)
                offB[g][ks] = (uint32_t)(line*128 + ((((row & 1)*4 + 2*ks + jj) ^ (line & 7))*16));
        }
    }

    float acc[2][8][4];
    #pragma unroll
    for (int mi = 0; mi < 2; mi++)
        #pragma unroll
        for (int na = 0; na < 8; na++)
            #pragma unroll
            for (int i = 0; i < 4; i++) acc[mi][na][i] = 0.f;

    #pragma unroll
    for (int i = 0; i < 8; i++)
        cpasync16(sb + dsw[i], srcbase + soff[i]);
    CP_COMMIT();

    for (int c = 0; c < 64; c++){
        int p = c & 1;
        if (c + 1 < 64){
            uint32_t stg = sb + ((c + 1) & 1)*STG_BYTES;
            const char* s2 = srcbase + (size_t)(c + 1)*64;
            #pragma unroll
            for (int i = 0; i < 8; i++)
                cpasync16(stg + dsw[i], s2 + soff[i]);
            CP_COMMIT();
            CP_WAIT(1);
        } else {
            CP_WAIT(0);
        }
        __syncthreads();

        uint32_t base = sb + p*STG_BYTES;
        uint32_t Ah = base, Al = base + 8192, Bh = base + 16384, Bl = base + 24576;
        #pragma unroll
        for (int ks = 0; ks < 2; ks++){
            uint32_t ah[2][4], al[2][4], bh[4][4], bl[4][4];
            #pragma unroll
            for (int mi = 0; mi < 2; mi++){
                ldm_x4(ah[mi][0], ah[mi][1], ah[mi][2], ah[mi][3], Ah + offA[mi][ks]);
                ldm_x4(al[mi][0], al[mi][1], al[mi][2], al[mi][3], Al + offA[mi][ks]);
            }
            #pragma unroll
            for (int g = 0; g < 4; g++){
                ldm_x4(bh[g][0], bh[g][1], bh[g][2], bh[g][3], Bh + offB[g][ks]);
                ldm_x4(bl[g][0], bl[g][1], bl[g][2], bl[g][3], Bl + offB[g][ks]);
            }
            #pragma unroll
            for (int mi = 0; mi < 2; mi++){
                #pragma unroll
                for (int na = 0; na < 8; na++){
                    int g = na >> 1, o = na & 1;
                    mma_bf16(acc[mi][na], ah[mi], bh[g][o], bh[g][o + 2]);
                    mma_bf16(acc[mi][na], ah[mi], bl[g][o], bl[g][o + 2]);
                    mma_bf16(acc[mi][na], al[mi], bh[g][o], bh[g][o + 2]);
                }
            }
        }
        __syncthreads();
    }

    #pragma unroll
    for (int mi = 0; mi < 2; mi++){
        #pragma unroll
        for (int na = 0; na < 8; na++){
            int r  = row0 + wm*32 + mi*16 + (l >> 2);
            int cc = col0 + wn*64 + na*8 + (l & 3)*2;
            *(float2*)(out + (size_t)r*Dz + cc)       = make_float2(acc[mi][na][0], acc[mi][na][1]);
            *(float2*)(out + (size_t)(r + 8)*Dz + cc) = make_float2(acc[mi][na][2], acc[mi][na][3]);
        }
    }
}

// ---------------- launch ----------------------------------------------------
extern "C" void kernel_launch(void* const* d_in, const int* in_sizes, int n_in,
                              void* d_out, int out_size){
    const float* inter   = (const float*)d_in[0];
    const int*   lengths = (const int*)  d_in[1];
    const float* W       = (const float*)d_in[2];
    const float* cur_a   = (const float*)d_in[3];
    const float* nb_a    = (const float*)d_in[4];
    const float* W_out   = (const float*)d_in[5];
    float* out = (float*)d_out;

    cudaFuncSetAttribute(attn_kernel, cudaFuncAttributeMaxDynamicSharedMemorySize, SMEM_ATTN);
    cudaFuncSetAttribute(out_gemm_kernel, cudaFuncAttributeMaxDynamicSharedMemorySize, SMEM_G3);

    prep_vecs_kernel<<<16, Dz>>>(W, cur_a, nb_a);
    prep_M2_kernel<<<KTOT, Dz>>>(W, W_out);
    attn_kernel<<<Bz, 256, SMEM_ATTN>>>(inter, lengths, out);
    dim3 g3(Bz/128, Dz/128);
    out_gemm_kernel<<<g3, 256, SMEM_G3>>>(out);
}